// round 17
// baseline (speedup 1.0000x reference)
#include <cuda_runtime.h>
#include <math.h>

// B=2048, T=64, IN=8, HID=6 qubits, OUT=8, NLAYERS=2, concat=16
#define NB    2048
#define NT    64
#define NIN   8
#define NHID  6
#define NOUT  8
#define NCAT  16
#define NLAY  2

__device__ float g_xpre[NB * NT * NHID];

__device__ __forceinline__ float sigmoidf_(float v) {
    return 1.0f / (1.0f + __expf(-v));
}
__device__ __forceinline__ float tanhfast_(float v) {
    return 2.0f / (1.0f + __expf(-2.0f * v)) - 1.0f;
}

// ---- packed f32x2 helpers (sm_100+) ----
__device__ __forceinline__ unsigned long long pk2(float lo, float hi) {
    unsigned long long d;
    asm("mov.b64 %0, {%1, %2};" : "=l"(d) : "f"(lo), "f"(hi));
    return d;
}
__device__ __forceinline__ void upk2(unsigned long long v, float& lo, float& hi) {
    asm("mov.b64 {%0, %1}, %2;" : "=f"(lo), "=f"(hi) : "l"(v));
}
__device__ __forceinline__ unsigned long long fma2_(unsigned long long a,
                                                    unsigned long long b,
                                                    unsigned long long c) {
    unsigned long long d;
    asm("fma.rn.f32x2 %0, %1, %2, %3;" : "=l"(d) : "l"(a), "l"(b), "l"(c));
    return d;
}
__device__ __forceinline__ unsigned long long mul2_(unsigned long long a,
                                                    unsigned long long b) {
    unsigned long long d;
    asm("mul.rn.f32x2 %0, %1, %2;" : "=l"(d) : "l"(a), "l"(b));
    return d;
}

// Prepass: one thread per (b,t); computes the 6 x-dependent partial angles.
__global__ __launch_bounds__(256) void xpre_kernel(
    const float* __restrict__ x,
    const float* __restrict__ W_in,
    const float* __restrict__ b_in)
{
    int idx = blockIdx.x * blockDim.x + threadIdx.x;
    if (idx >= NB * NT) return;
    float4 xa = *reinterpret_cast<const float4*>(x + (size_t)idx * NIN);
    float4 xb = *reinterpret_cast<const float4*>(x + (size_t)idx * NIN + 4);
    #pragma unroll
    for (int w = 0; w < NHID; w++) {
        const float* wr = W_in + w * NCAT + 8;
        float acc = b_in[w];
        acc = fmaf(wr[0], xa.x, acc);
        acc = fmaf(wr[1], xa.y, acc);
        acc = fmaf(wr[2], xa.z, acc);
        acc = fmaf(wr[3], xa.w, acc);
        acc = fmaf(wr[4], xb.x, acc);
        acc = fmaf(wr[5], xb.y, acc);
        acc = fmaf(wr[6], xb.z, acc);
        acc = fmaf(wr[7], xb.w, acc);
        g_xpre[idx * NHID + w] = acc;
    }
}

// ONE warp = TWO batch elements (independent interleaved chains; all weight
// constants shared). Per element: 4 octets = 4 gate circuits; wires 0,1,2 ->
// lane bits 2,1,0; wires 3,4,5 -> in-thread amp bits. All folds of R16 kept.
// y-linear packed across elements; expval butterflies packed across elements.
__global__ __launch_bounds__(128, 2) void qlstm_kernel(
    const float* __restrict__ W_in,
    const float* __restrict__ W_out,
    const float* __restrict__ b_out,
    const float* __restrict__ wf,
    const float* __restrict__ wi,
    const float* __restrict__ wg,
    const float* __restrict__ wo,
    float* __restrict__ out)
{
    __shared__ float2 sCS2[4][NHID];

    const int tid = threadIdx.x;
    if (tid < 4 * NHID) {
        const float* wp[4] = {wf, wi, wg, wo};
        int g = tid / NHID;
        int w = tid % NHID;
        float s_, c_;
        sincosf(0.5f * wp[g][NHID + w], &s_, &c_);
        sCS2[g][w] = make_float2(c_, s_);
    }
    __syncthreads();

    const unsigned FULL = 0xffffffffu;
    const int lane = tid & 31;
    const int warp = blockIdx.x * (blockDim.x >> 5) + (tid >> 5);
    const int bA   = warp * 2;             // element A
    const int bB   = bA + 1;               // element B
    const int oct  = lane >> 3;
    const int q    = lane & 7;
    const int oct6 = oct * 6;

    const int ibx0 = (q >> 2) & 1;
    const int ibx1 = (q >> 1) & 1;
    const int ibx2 = q & 1;
    const bool bx0 = ibx0, bx2 = ibx2;

    const int gl = lane / 6;
    const int wlane = lane - 6 * gl;
    const bool aln = (lane < 24);

    // Hoisted weights (shared across both elements)
    unsigned long long winh2[8];           // (w, w) packed for dual-y fma
    float th2;
    {
        int row = aln ? wlane : 0;
        #pragma unroll
        for (int j = 0; j < 8; j++) {
            float wv = W_in[row * NCAT + j];
            winh2[j] = pk2(wv, wv);
        }
        const float* wp[4] = {wf, wi, wg, wo};
        th2 = aln ? 0.5f * wp[gl][wlane] : 0.0f;
    }
    float wrow[NHID];
    {
        float s01  = ((ibx0 + ibx1) & 1) ? -1.0f : 1.0f;
        float s12  = ((ibx1 + ibx2) & 1) ? -1.0f : 1.0f;
        float s012 = ((ibx0 + ibx1 + ibx2) & 1) ? -1.0f : 1.0f;
        wrow[0] = W_out[q * NHID + 0] * s12;
        wrow[1] = W_out[q * NHID + 1] * s01;
        wrow[2] = W_out[q * NHID + 2] * s012;
        wrow[3] = W_out[q * NHID + 3] * s012;
        wrow[4] = W_out[q * NHID + 4] * s012;
        wrow[5] = W_out[q * NHID + 5] * s012;
    }
    const float bj = b_out[q];

    unsigned long long sgn2[4];
    #pragma unroll
    for (int p = 0; p < 4; p++) {
        float sg[2];
        #pragma unroll
        for (int s = 0; s < 2; s++) {
            int a = 2 * p + s;
            int a0 = a & 1, a1 = (a >> 1) & 1, a2 = (a >> 2) & 1;
            int z0 = ibx0 ^ a0;
            int z1 = ibx1 ^ ibx0 ^ a0;
            int z2 = ibx2 ^ ibx1;
            int z3 = a2 ^ ibx2;
            int z4 = a1 ^ a2;
            int z5 = a0 ^ a1;
            int k = (z0 + z1 + z2 + z3 + z4 + z5) & 3;
            sg[s] = (k == 0 || k == 3) ? 1.0f : -1.0f;
        }
        sgn2[p] = pk2(sg[0], sg[1]);
    }
    const bool x01 = (ibx1 ^ ibx0) != 0;
    const bool x12 = (ibx2 ^ ibx1) != 0;

    unsigned long long cc2[5], ss2[5], sn2[5];
    unsigned long long cs0pk, ns0pk;
    float A5, B5, K5;
    {
        #pragma unroll
        for (int w = 1; w < 5; w++) {
            float2 cs = sCS2[oct][w];
            cc2[w] = pk2(cs.x, cs.x);
            ss2[w] = pk2(cs.y, cs.y);
            sn2[w] = pk2(-cs.y, -cs.y);
        }
        float2 csw0 = sCS2[oct][0];
        cs0pk = pk2(csw0.x, csw0.y);
        ns0pk = pk2(-csw0.y, csw0.x);
        float2 csw5 = sCS2[oct][5];
        A5 = csw5.x * csw5.x;
        B5 = csw5.y * csw5.y;
        K5 = 2.0f * csw5.x * csw5.y;
    }
    const unsigned long long NEG1 = pk2(-1.0f, -1.0f);

    float* orowA = out + (size_t)bA * NT * NOUT;
    float* orowB = out + (size_t)bB * NT * NOUT;
    const float* prepA = g_xpre + (size_t)bA * NT * NHID;
    const float* prepB = g_xpre + (size_t)bB * NT * NHID;

    float hsA = 0.0f, csA = 0.0f, hsB = 0.0f, csB = 0.0f;
    float preA = aln ? prepA[wlane] : 0.0f;
    float preB = aln ? prepB[wlane] : 0.0f;

    #pragma unroll 1
    for (int t = 0; t < NT; t++) {
        // ---- dual y-linear, packed across elements ----
        unsigned long long ypk = pk2(preA, preB);
        unsigned long long hpk = pk2(hsA, hsB);
        #pragma unroll
        for (int j = 0; j < 8; j++) {
            unsigned long long hj = __shfl_sync(FULL, hpk, j);
            ypk = fma2_(winh2[j], hj, ypk);
        }
        float yA, yB;
        upk2(ypk, yA, yB);
        float preAn = 0.0f, preBn = 0.0f;
        if (t + 1 < NT && aln) {
            preAn = prepA[(t + 1) * NHID + wlane];
            preBn = prepB[(t + 1) * NHID + wlane];
        }

        float mySA, myCA, mySB, myCB;
        __sincosf(fmaf(0.5f, yA, th2), &mySA, &myCA);
        __sincosf(fmaf(0.5f, yB, th2), &mySB, &myCB);
        float cw[2][NHID], sw[2][NHID];
        #pragma unroll
        for (int w = 0; w < NHID; w++) {
            cw[0][w] = __shfl_sync(FULL, myCA, oct6 + w);
            sw[0][w] = __shfl_sync(FULL, mySA, oct6 + w);
            cw[1][w] = __shfl_sync(FULL, myCB, oct6 + w);
            sw[1][w] = __shfl_sync(FULL, mySB, oct6 + w);
        }

        // ---- per-element construct + RX2 (interleaved chains) ----
        unsigned long long R[2][4], I[2][4];
        #pragma unroll
        for (int e = 0; e < 2; e++) {
            float F0_0 = bx0 ? sw[e][0] : cw[e][0];
            float F0_1 = bx0 ? cw[e][0] : sw[e][0];
            float F1_0 = x01 ? sw[e][1] : cw[e][1];
            float F1_1 = x01 ? cw[e][1] : sw[e][1];
            float f2v  = x12 ? sw[e][2] : cw[e][2];
            float G0 = F0_0 * F1_0 * f2v;
            float G1 = F0_1 * F1_1 * f2v;
            float F3_0 = bx2 ? sw[e][3] : cw[e][3];
            float F3_1 = bx2 ? cw[e][3] : sw[e][3];
            const float M00 = cw[e][4] * cw[e][5];
            const float M01 = cw[e][4] * sw[e][5];
            const float M10 = sw[e][4] * cw[e][5];
            const float M11 = sw[e][4] * sw[e][5];

            unsigned long long GG  = pk2(G0, G1);
            unsigned long long F3e = pk2(F3_0, F3_0);
            unsigned long long F3o = pk2(F3_1, F3_1);
            unsigned long long V[4];
            V[0] = mul2_(mul2_(GG, F3e), mul2_(pk2(M00, M01), sgn2[0]));
            V[1] = mul2_(mul2_(GG, F3e), mul2_(pk2(M11, M10), sgn2[1]));
            V[2] = mul2_(mul2_(GG, F3o), mul2_(pk2(M10, M11), sgn2[2]));
            V[3] = mul2_(mul2_(GG, F3o), mul2_(pk2(M01, M00), sgn2[3]));

            // sparse packed wire-0
            #pragma unroll
            for (int p = 0; p < 4; p++) {
                unsigned long long Vx = __shfl_xor_sync(FULL, V[p], 4);
                float vl, vh, xl, xh;
                upk2(V[p], vl, vh);
                upk2(Vx, xl, xh);
                R[e][p] = mul2_(cs0pk, pk2(vl, xh));
                I[e][p] = mul2_(ns0pk, pk2(xl, vh));
            }
        }

        // wires 1,2 — both elements interleaved per stage
        #pragma unroll
        for (int w = 1; w < 3; w++) {
            const int m = 4 >> w;
            unsigned long long Rp[2][4], Ip[2][4];
            #pragma unroll
            for (int e = 0; e < 2; e++)
                #pragma unroll
                for (int p = 0; p < 4; p++) {
                    Rp[e][p] = __shfl_xor_sync(FULL, R[e][p], m);
                    Ip[e][p] = __shfl_xor_sync(FULL, I[e][p], m);
                }
            #pragma unroll
            for (int e = 0; e < 2; e++)
                #pragma unroll
                for (int p = 0; p < 4; p++) {
                    R[e][p] = fma2_(cc2[w], R[e][p], mul2_(ss2[w], Ip[e][p]));
                    I[e][p] = fma2_(cc2[w], I[e][p], mul2_(sn2[w], Rp[e][p]));
                }
        }
        // wires 3,4 (in-thread)
        #pragma unroll
        for (int w = 3; w < 5; w++) {
            const int pm = (w == 3) ? 2 : 1;
            #pragma unroll
            for (int e = 0; e < 2; e++) {
                unsigned long long nR[4], nI[4];
                #pragma unroll
                for (int p = 0; p < 4; p++) {
                    nR[p] = fma2_(cc2[w], R[e][p], mul2_(ss2[w], I[e][p ^ pm]));
                    nI[p] = fma2_(cc2[w], I[e][p], mul2_(sn2[w], R[e][p ^ pm]));
                }
                #pragma unroll
                for (int p = 0; p < 4; p++) { R[e][p] = nR[p]; I[e][p] = nI[p]; }
            }
        }

        // ---- wire-5-folded probabilities, per element ----
        float pr[2][8];
        #pragma unroll
        for (int e = 0; e < 2; e++)
            #pragma unroll
            for (int k = 0; k < 4; k++) {
                unsigned long long N = fma2_(I[e][k], I[e][k], mul2_(R[e][k], R[e][k]));
                float n0, n1, r0, r1, i0, i1;
                upk2(N, n0, n1);
                upk2(R[e][k], r0, r1);
                upk2(I[e][k], i0, i1);
                float wk = fmaf(r0, i1, -(i0 * r1));
                float tk = K5 * wk;
                pr[e][2 * k]     = fmaf(A5, n0, fmaf(B5, n1, tk));
                pr[e][2 * k + 1] = fmaf(B5, n0, fmaf(A5, n1, -tk));
            }

        // ---- expval butterflies, packed ACROSS ELEMENTS (same masks) ----
        unsigned long long UA, U3, U4, U5;
        {
            float uAe[2], u3e[2], u4e[2], u5e[2];
            #pragma unroll
            for (int e = 0; e < 2; e++) {
                float* p = pr[e];
                float t01 = p[0] + p[1], t23 = p[2] + p[3];
                float t45 = p[4] + p[5], t67 = p[6] + p[7];
                float slo = t01 + t23, shi = t45 + t67;
                uAe[e] = slo + shi;
                u3e[e] = slo - shi;
                u4e[e] = (t01 + t67) - (t23 + t45);
                u5e[e] = ((p[0] + p[3]) + (p[5] + p[6]))
                       - ((p[1] + p[2]) + (p[4] + p[7]));
            }
            UA = pk2(uAe[0], uAe[1]);
            U3 = pk2(u3e[0], u3e[1]);
            U4 = pk2(u4e[0], u4e[1]);
            U5 = pk2(u5e[0], u5e[1]);
        }
        unsigned long long TA, T3, T4, T5;
        // stage 1
        TA = __shfl_xor_sync(FULL, UA, 4);
        T3 = __shfl_xor_sync(FULL, U3, 4);
        T4 = __shfl_xor_sync(FULL, U4, 4);
        T5 = __shfl_xor_sync(FULL, U5, 2);
        UA = fma2_(TA, NEG1, UA);
        U3 = fma2_(T3, NEG1, U3);
        U4 = fma2_(T4, NEG1, U4);
        U5 = fma2_(T5, NEG1, U5);
        // stage 2
        TA = __shfl_xor_sync(FULL, UA, 2);
        T3 = __shfl_xor_sync(FULL, U3, 2);
        T4 = __shfl_xor_sync(FULL, U4, 2);
        T5 = __shfl_xor_sync(FULL, U5, 1);
        UA = fma2_(TA, NEG1, UA);
        U3 = fma2_(T3, NEG1, U3);
        U4 = fma2_(T4, NEG1, U4);
        U5 = fma2_(T5, NEG1, U5);
        // stage 3 partners
        TA = __shfl_xor_sync(FULL, UA, 1);
        T3 = __shfl_xor_sync(FULL, U3, 1);
        T4 = __shfl_xor_sync(FULL, U4, 1);
        T5 = __shfl_xor_sync(FULL, U5, 4);

        float acc[2];
        {
            float uAs[2], tAs[2], u3s[2], t3s[2], u4s[2], t4s[2], u5s[2], t5s[2];
            upk2(UA, uAs[0], uAs[1]); upk2(TA, tAs[0], tAs[1]);
            upk2(U3, u3s[0], u3s[1]); upk2(T3, t3s[0], t3s[1]);
            upk2(U4, u4s[0], u4s[1]); upk2(T4, t4s[0], t4s[1]);
            upk2(U5, u5s[0], u5s[1]); upk2(T5, t5s[0], t5s[1]);
            #pragma unroll
            for (int e = 0; e < 2; e++) {
                float E1 = uAs[e] + tAs[e];
                float E2 = uAs[e] - tAs[e];
                float E3 = u3s[e] - t3s[e];
                float E4 = u4s[e] - t4s[e];
                float E0 = u5s[e] + t5s[e];
                float E5 = u5s[e] - t5s[e];
                float a2 = bj;
                a2 = fmaf(wrow[0], E0, a2);
                a2 = fmaf(wrow[1], E1, a2);
                a2 = fmaf(wrow[2], E2, a2);
                a2 = fmaf(wrow[3], E3, a2);
                a2 = fmaf(wrow[4], E4, a2);
                a2 = fmaf(wrow[5], E5, a2);
                acc[e] = a2;
            }
        }

        // ---- gather gates (packed: both elements in one b64) ----
        unsigned long long accpk = pk2(acc[0], acc[1]);
        unsigned long long afp = __shfl_sync(FULL, accpk, q);
        unsigned long long aip = __shfl_sync(FULL, accpk, 8 | q);
        unsigned long long agp = __shfl_sync(FULL, accpk, 16 | q);
        unsigned long long aop = __shfl_sync(FULL, accpk, 24 | q);
        float afA, afB, aiA, aiB, agA, agB, aoA, aoB;
        upk2(afp, afA, afB);
        upk2(aip, aiA, aiB);
        upk2(agp, agA, agB);
        upk2(aop, aoA, aoB);

        {
            float fg = sigmoidf_(afA);
            float ig = sigmoidf_(aiA);
            float gg = tanhfast_(agA);
            float og = sigmoidf_(aoA);
            csA = fmaf(fg, csA, ig * gg);
            hsA = og * tanhfast_(csA);
        }
        {
            float fg = sigmoidf_(afB);
            float ig = sigmoidf_(aiB);
            float gg = tanhfast_(agB);
            float og = sigmoidf_(aoB);
            csB = fmaf(fg, csB, ig * gg);
            hsB = og * tanhfast_(csB);
        }

        if (lane < NOUT) orowA[t * NOUT + q] = hsA;
        else if (lane < 16) orowB[t * NOUT + q] = hsB;
        preA = preAn;
        preB = preBn;
    }
}

extern "C" void kernel_launch(void* const* d_in, const int* in_sizes, int n_in,
                              void* d_out, int out_size) {
    (void)in_sizes; (void)n_in; (void)out_size;
    xpre_kernel<<<(NB * NT + 255) / 256, 256>>>(
        (const float*)d_in[0],   // x
        (const float*)d_in[1],   // W_in
        (const float*)d_in[2]);  // b_in
    // 2 elements/warp, 4 warps/block -> 256 blocks, 1024 warps
    qlstm_kernel<<<NB / 8, 128>>>(
        (const float*)d_in[1],   // W_in (h part)
        (const float*)d_in[3],   // W_out
        (const float*)d_in[4],   // b_out
        (const float*)d_in[5],   // wf
        (const float*)d_in[6],   // wi
        (const float*)d_in[7],   // wg
        (const float*)d_in[8],   // wo
        (float*)d_out);
}